// round 1
// baseline (speedup 1.0000x reference)
#include <cuda_runtime.h>

#define N_NODES 100000
#define N_EDGES 1600000
#define D 64
#define N_RELS 200
#define SLOPE 0.01f

// Scratch (static device globals — no allocation in kernel_launch)
__device__ float        g_hW[N_NODES * D];     // h @ W[:D]
__device__ float        g_relW[N_RELS * D];    // rel_emb @ W[D:]
__device__ float        g_ssrc[N_NODES];
__device__ float        g_sdst[N_NODES];
__device__ float        g_srel[N_RELS];
__device__ unsigned int g_mkey[N_NODES];       // ordered-uint encoded segment max
__device__ float        g_den[N_NODES];
__device__ int          g_deg[N_NODES];
__device__ float        g_edge[N_EDGES];       // score, then exp(score - m)

// Monotone float -> uint mapping so atomicMax(uint) == float max
__device__ __forceinline__ unsigned int fkey(float f) {
    unsigned int u = __float_as_uint(f);
    return (u & 0x80000000u) ? ~u : (u | 0x80000000u);
}
__device__ __forceinline__ float funkey(unsigned int k) {
    return (k & 0x80000000u) ? __uint_as_float(k ^ 0x80000000u)
                             : __uint_as_float(~k);
}

// ---------------------------------------------------------------------------
// 0) init: zero out (poisoned by harness) + per-node accumulators
__global__ void k_init(float* __restrict__ out) {
    int i = blockIdx.x * blockDim.x + threadIdx.x;
    if (i < N_NODES * D) out[i] = 0.0f;
    if (i < N_NODES) {
        g_mkey[i] = 0u;     // maps to the most-negative float under funkey
        g_den[i]  = 0.0f;
        g_deg[i]  = 0;
    }
}

// 1) hW = h @ Wn[:D]  (4 nodes per 256-thread block, Wn in shared)
__global__ void k_hw(const float* __restrict__ h, const float* __restrict__ Wn) {
    __shared__ float sW[D * D];
    __shared__ float sh[4][D];
    int t = threadIdx.x;
    #pragma unroll
    for (int i = t; i < D * D; i += 256) sW[i] = Wn[i];
    int l = t >> 6, j = t & 63;
    int node = blockIdx.x * 4 + l;
    sh[l][j] = h[node * D + j];
    __syncthreads();
    float acc = 0.0f;
    #pragma unroll
    for (int k = 0; k < D; k++) acc = fmaf(sh[l][k], sW[k * D + j], acc);
    g_hW[node * D + j] = acc;
}

// 2) s_src = h@a1, s_dst = h@a2  (one warp per node)
__global__ void k_s(const float* __restrict__ h, const float* __restrict__ attn) {
    int w    = (blockIdx.x * blockDim.x + threadIdx.x) >> 5;
    int lane = threadIdx.x & 31;
    if (w >= N_NODES) return;
    float v0 = h[w * D + lane];
    float v1 = h[w * D + 32 + lane];
    float p1 = v0 * attn[lane]      + v1 * attn[lane + 32];
    float p2 = v0 * attn[64 + lane] + v1 * attn[96 + lane];
    #pragma unroll
    for (int o = 16; o; o >>= 1) {
        p1 += __shfl_down_sync(0xffffffffu, p1, o);
        p2 += __shfl_down_sync(0xffffffffu, p2, o);
    }
    if (lane == 0) { g_ssrc[w] = p1; g_sdst[w] = p2; }
}

// 3) relW = rel_emb @ Wn[D:], s_rel = rel_emb @ a3  (one block per relation)
__global__ void k_rel(const float* __restrict__ rel, const float* __restrict__ Wn,
                      const float* __restrict__ attn) {
    __shared__ float sr[D];
    int r = blockIdx.x, j = threadIdx.x;
    sr[j] = rel[r * D + j];
    __syncthreads();
    float acc = 0.0f;
    #pragma unroll
    for (int k = 0; k < D; k++) acc = fmaf(sr[k], Wn[(D + k) * D + j], acc);
    g_relW[r * D + j] = acc;
    if (j == 0) {
        float s = 0.0f;
        #pragma unroll
        for (int k = 0; k < D; k++) s = fmaf(sr[k], attn[128 + k], s);
        g_srel[r] = s;
    }
}

// 4) edge pass A: score = -etime*delta*leaky_relu(...); segment max + deg flag
__global__ void k_edgeA(const float* __restrict__ etime, const int* __restrict__ src,
                        const int* __restrict__ dst, const int* __restrict__ etype,
                        const float* __restrict__ delta) {
    int e = blockIdx.x * blockDim.x + threadIdx.x;
    if (e >= N_EDGES) return;
    int dd = dst[e];
    float v = g_ssrc[src[e]] + g_sdst[dd] + g_srel[etype[e]];
    v = v > 0.0f ? v : SLOPE * v;
    float score = -etime[e] * delta[0] * v;
    g_edge[e] = score;
    atomicMax(&g_mkey[dd], fkey(score));
    g_deg[dd] = 1;   // idempotent store, no atomic needed
}

// 5) edge pass B: ex = exp(score - m[dst]); segment sum of ex
__global__ void k_edgeB(const int* __restrict__ dst) {
    int e = blockIdx.x * blockDim.x + threadIdx.x;
    if (e >= N_EDGES) return;
    int dd = dst[e];
    float ex = expf(g_edge[e] - funkey(g_mkey[dd]));
    g_edge[e] = ex;
    atomicAdd(&g_den[dd], ex);
}

// 6) edge pass C: out[dst] += (ex/den[dst]) * (hW[src] + relW[etype])
//    64 threads per edge (j = feature index); warp shares one edge's scalars.
__global__ void k_edgeC(const int* __restrict__ src, const int* __restrict__ dst,
                        const int* __restrict__ etype, float* __restrict__ out) {
    long long gid = (long long)blockIdx.x * blockDim.x + threadIdx.x;
    int e = (int)(gid >> 6);
    int j = (int)(gid & 63);
    if (e >= N_EDGES) return;
    int dd = __ldg(&dst[e]);
    float w = __fdividef(g_edge[e], g_den[dd]);
    float msg = g_hW[__ldg(&src[e]) * D + j] + g_relW[__ldg(&etype[e]) * D + j];
    atomicAdd(&out[dd * D + j], w * msg);
}

// 7) final: out = (has_in ? agg : h) + h @ (has_in ? loop_W : evolve_loop_W)
__global__ void k_final(const float* __restrict__ h, const float* __restrict__ Wl,
                        const float* __restrict__ We, float* __restrict__ out) {
    __shared__ float sWl[D * D];
    __shared__ float sWe[D * D];
    __shared__ float sh[4][D];
    int t = threadIdx.x;
    #pragma unroll
    for (int i = t; i < D * D; i += 256) { sWl[i] = Wl[i]; sWe[i] = We[i]; }
    int l = t >> 6, j = t & 63;
    int node = blockIdx.x * 4 + l;
    sh[l][j] = h[node * D + j];
    __syncthreads();
    bool has = (g_deg[node] != 0);
    const float* W = has ? sWl : sWe;
    float acc = 0.0f;
    #pragma unroll
    for (int k = 0; k < D; k++) acc = fmaf(sh[l][k], W[k * D + j], acc);
    float base = has ? out[node * D + j] : sh[l][j];
    out[node * D + j] = base + acc;
}

extern "C" void kernel_launch(void* const* d_in, const int* in_sizes, int n_in,
                              void* d_out, int out_size) {
    const float* h     = (const float*)d_in[0];
    const float* rel   = (const float*)d_in[1];
    const float* Wn    = (const float*)d_in[2];
    const float* attn  = (const float*)d_in[3];
    const float* delta = (const float*)d_in[4];
    const float* Wl    = (const float*)d_in[5];
    const float* We    = (const float*)d_in[6];
    const float* etime = (const float*)d_in[7];
    const int*   src   = (const int*)d_in[8];
    const int*   dst   = (const int*)d_in[9];
    const int*   etype = (const int*)d_in[10];
    float* out = (float*)d_out;

    k_init <<<25000, 256>>>(out);                       // covers N_NODES*D = 6.4M
    k_hw   <<<25000, 256>>>(h, Wn);                     // 100000 / 4 nodes per block
    k_s    <<<12500, 256>>>(h, attn);                   // 100000 warps
    k_rel  <<<N_RELS, 64>>>(rel, Wn, attn);
    k_edgeA<<<6250, 256>>>(etime, src, dst, etype, delta);
    k_edgeB<<<6250, 256>>>(dst);
    k_edgeC<<<400000, 256>>>(src, dst, etype, out);     // N_EDGES * 64 threads
    k_final<<<25000, 256>>>(h, Wl, We, out);
}

// round 6
// speedup vs baseline: 1.6276x; 1.6276x over previous
#include <cuda_runtime.h>

#define N_NODES 100000
#define N_EDGES 1600000
#define D 64
#define N_RELS 200
#define SLOPE 0.01f

// Scratch (static device globals — no allocation in kernel_launch)
__device__ float g_hW[N_NODES * D];     // h @ W[:D]
__device__ float g_relW[N_RELS * D];    // rel_emb @ W[D:]
__device__ float g_ssrc[N_NODES];
__device__ float g_sdst[N_NODES];
__device__ float g_srel[N_RELS];
__device__ float g_den[N_NODES];        // segment sum of exp(score); >0 iff deg>0
__device__ float g_edge[N_EDGES];       // exp(score)

__device__ __forceinline__ void red_add_v4(float* addr, float4 v) {
    asm volatile("red.global.add.v4.f32 [%0], {%1,%2,%3,%4};"
                 :: "l"(addr), "f"(v.x), "f"(v.y), "f"(v.z), "f"(v.w)
                 : "memory");
}

// ---------------------------------------------------------------------------
// 0) init: zero out (harness poisons it) + den
__global__ void k_init(float* __restrict__ out) {
    int i = blockIdx.x * blockDim.x + threadIdx.x;
    if (i < N_NODES * D) out[i] = 0.0f;
    if (i < N_NODES) g_den[i] = 0.0f;
}

// 1) hW = h @ Wn[:D]; s_src = h@a1; s_dst = h@a2.
//    4 nodes per 256-thread block; node l owns threads [64l, 64l+64) = warps 2l,2l+1.
__global__ void k_hw_s(const float* __restrict__ h, const float* __restrict__ Wn,
                       const float* __restrict__ attn) {
    __shared__ float sW[D * D];
    __shared__ float sh[4][D];
    __shared__ float part1[8], part2[8];
    int t = threadIdx.x;
    #pragma unroll
    for (int i = t; i < D * D; i += 256) sW[i] = Wn[i];
    int l = t >> 6, j = t & 63;
    int node = blockIdx.x * 4 + l;
    float v = h[node * D + j];
    sh[l][j] = v;

    // attention partials (reduced over j per node)
    float p1 = v * attn[j];
    float p2 = v * attn[D + j];
    #pragma unroll
    for (int o = 16; o; o >>= 1) {
        p1 += __shfl_down_sync(0xffffffffu, p1, o);
        p2 += __shfl_down_sync(0xffffffffu, p2, o);
    }
    int w = t >> 5;
    if ((t & 31) == 0) { part1[w] = p1; part2[w] = p2; }
    __syncthreads();
    if (j == 0) {
        g_ssrc[node] = part1[2 * l] + part1[2 * l + 1];
        g_sdst[node] = part2[2 * l] + part2[2 * l + 1];
    }
    float acc = 0.0f;
    #pragma unroll
    for (int k = 0; k < D; k++) acc = fmaf(sh[l][k], sW[k * D + j], acc);
    g_hW[node * D + j] = acc;
}

// 2) relW = rel_emb @ Wn[D:], s_rel = rel_emb @ a3  (one block per relation)
__global__ void k_rel(const float* __restrict__ rel, const float* __restrict__ Wn,
                      const float* __restrict__ attn) {
    __shared__ float sr[D];
    int r = blockIdx.x, j = threadIdx.x;
    sr[j] = rel[r * D + j];
    __syncthreads();
    float acc = 0.0f;
    #pragma unroll
    for (int k = 0; k < D; k++) acc = fmaf(sr[k], Wn[(D + k) * D + j], acc);
    g_relW[r * D + j] = acc;
    if (j == 0) {
        float s = 0.0f;
        #pragma unroll
        for (int k = 0; k < D; k++) s = fmaf(sr[k], attn[2 * D + k], s);
        g_srel[r] = s;
    }
}

// 3) fused edge pass: ex = exp(score) (no max shift needed: |score| <~ 15,
//    exp stays far from fp32 overflow; softmax ratio is shift-invariant);
//    segment-sum of ex into den.
__global__ void k_edge1(const float* __restrict__ etime, const int* __restrict__ src,
                        const int* __restrict__ dst, const int* __restrict__ etype,
                        const float* __restrict__ delta) {
    int e = blockIdx.x * blockDim.x + threadIdx.x;
    if (e >= N_EDGES) return;
    int dd = dst[e];
    float v = g_ssrc[src[e]] + g_sdst[dd] + g_srel[etype[e]];
    v = v > 0.0f ? v : SLOPE * v;
    float ex = __expf(-etime[e] * delta[0] * v);
    g_edge[e] = ex;
    atomicAdd(&g_den[dd], ex);
}

// 4) aggregate: out[dst] += (ex/den[dst]) * (hW[src] + relW[etype])
//    16 threads per edge, float4 lanes, vector RED into out.
//    Edge scalars loaded once per 16-lane group (lane q==0) and broadcast.
__global__ void k_edge2(const int* __restrict__ src, const int* __restrict__ dst,
                        const int* __restrict__ etype, float* __restrict__ out) {
    int gid = blockIdx.x * blockDim.x + threadIdx.x;
    int e = gid >> 4;
    int q = gid & 15;
    if (e >= N_EDGES) return;
    int base = threadIdx.x & 16;  // lane id of q==0 within this half-warp group

    int dd = 0, s = 0, r = 0;
    float w = 0.0f;
    if (q == 0) {
        dd = __ldg(&dst[e]);
        s  = __ldg(&src[e]);
        r  = __ldg(&etype[e]);
        w  = __fdividef(g_edge[e], g_den[dd]);
    }
    dd = __shfl_sync(0xffffffffu, dd, base);
    s  = __shfl_sync(0xffffffffu, s,  base);
    r  = __shfl_sync(0xffffffffu, r,  base);
    w  = __shfl_sync(0xffffffffu, w,  base);

    float4 hv = *(const float4*)&g_hW[s * D + q * 4];
    float4 rv = *(const float4*)&g_relW[r * D + q * 4];
    float4 m;
    m.x = w * (hv.x + rv.x);
    m.y = w * (hv.y + rv.y);
    m.z = w * (hv.z + rv.z);
    m.w = w * (hv.w + rv.w);
    red_add_v4(&out[dd * D + q * 4], m);
}

// 5) final: out = (has_in ? agg : h) + h @ (has_in ? loop_W : evolve_loop_W)
__global__ void k_final(const float* __restrict__ h, const float* __restrict__ Wl,
                        const float* __restrict__ We, float* __restrict__ out) {
    __shared__ float sWl[D * D];
    __shared__ float sWe[D * D];
    __shared__ float sh[4][D];
    int t = threadIdx.x;
    #pragma unroll
    for (int i = t; i < D * D; i += 256) { sWl[i] = Wl[i]; sWe[i] = We[i]; }
    int l = t >> 6, j = t & 63;
    int node = blockIdx.x * 4 + l;
    sh[l][j] = h[node * D + j];
    __syncthreads();
    bool has = (g_den[node] > 0.0f);
    const float* W = has ? sWl : sWe;
    float acc = 0.0f;
    #pragma unroll
    for (int k = 0; k < D; k++) acc = fmaf(sh[l][k], W[k * D + j], acc);
    float base = has ? out[node * D + j] : sh[l][j];
    out[node * D + j] = base + acc;
}

extern "C" void kernel_launch(void* const* d_in, const int* in_sizes, int n_in,
                              void* d_out, int out_size) {
    const float* h     = (const float*)d_in[0];
    const float* rel   = (const float*)d_in[1];
    const float* Wn    = (const float*)d_in[2];
    const float* attn  = (const float*)d_in[3];
    const float* delta = (const float*)d_in[4];
    const float* Wl    = (const float*)d_in[5];
    const float* We    = (const float*)d_in[6];
    const float* etime = (const float*)d_in[7];
    const int*   src   = (const int*)d_in[8];
    const int*   dst   = (const int*)d_in[9];
    const int*   etype = (const int*)d_in[10];
    float* out = (float*)d_out;

    k_init <<<25000, 256>>>(out);
    k_hw_s <<<25000, 256>>>(h, Wn, attn);
    k_rel  <<<N_RELS, 64>>>(rel, Wn, attn);
    k_edge1<<<6250, 256>>>(etime, src, dst, etype, delta);
    k_edge2<<<100000, 256>>>(src, dst, etype, out);   // N_EDGES*16 threads
    k_final<<<25000, 256>>>(h, Wl, We, out);
}

// round 7
// speedup vs baseline: 2.0632x; 1.2676x over previous
#include <cuda_runtime.h>

#define N_NODES 100000
#define N_EDGES 1600000
#define D 64
#define N_RELS 200
#define SLOPE 0.01f
#define SCAN_NB 196            // ceil(100000/512)

// Scratch (static device globals — no allocation anywhere)
__device__ float g_hW[N_NODES * D];      // h @ W[:D]
__device__ float g_relW[N_RELS * D];     // rel_emb @ W[D:]
__device__ float g_ssrc[N_NODES];
__device__ float g_sdst[N_NODES];
__device__ float g_srel[N_RELS];
__device__ int   g_cnt[N_NODES];         // dst histogram
__device__ int   g_off[N_NODES + 1];     // CSR offsets
__device__ int   g_cur[N_NODES];         // scatter cursors
__device__ int   g_bsum[SCAN_NB];        // scan block sums
__device__ int   g_pk[N_EDGES];          // dst-sorted packed (src<<8 | etype)
__device__ float g_ex[N_EDGES];          // dst-sorted exp(score)

__device__ __forceinline__ int warp_incl_scan(int v) {
    #pragma unroll
    for (int o = 1; o < 32; o <<= 1) {
        int t = __shfl_up_sync(0xffffffffu, v, o);
        if ((threadIdx.x & 31) >= o) v += t;
    }
    return v;
}

// ---------------------------------------------------------------------------
// 0) zero histogram
__global__ void k_zero() {
    int i = blockIdx.x * blockDim.x + threadIdx.x;
    if (i < N_NODES) g_cnt[i] = 0;
}

// 1) hW = h @ Wn[:D]; s_src = h@a1; s_dst = h@a2. 4 nodes / 256-thread block.
__global__ void k_hw_s(const float* __restrict__ h, const float* __restrict__ Wn,
                       const float* __restrict__ attn) {
    __shared__ float sW[D * D];
    __shared__ float sh[4][D];
    __shared__ float part1[8], part2[8];
    int t = threadIdx.x;
    #pragma unroll
    for (int i = t; i < D * D; i += 256) sW[i] = Wn[i];
    int l = t >> 6, j = t & 63;
    int node = blockIdx.x * 4 + l;
    float v = h[node * D + j];
    sh[l][j] = v;
    float p1 = v * attn[j];
    float p2 = v * attn[D + j];
    #pragma unroll
    for (int o = 16; o; o >>= 1) {
        p1 += __shfl_down_sync(0xffffffffu, p1, o);
        p2 += __shfl_down_sync(0xffffffffu, p2, o);
    }
    int w = t >> 5;
    if ((t & 31) == 0) { part1[w] = p1; part2[w] = p2; }
    __syncthreads();
    if (j == 0) {
        g_ssrc[node] = part1[2 * l] + part1[2 * l + 1];
        g_sdst[node] = part2[2 * l] + part2[2 * l + 1];
    }
    float acc = 0.0f;
    #pragma unroll
    for (int k = 0; k < D; k++) acc = fmaf(sh[l][k], sW[k * D + j], acc);
    g_hW[node * D + j] = acc;
}

// 2) relW = rel_emb @ Wn[D:], s_rel = rel_emb @ a3
__global__ void k_rel(const float* __restrict__ rel, const float* __restrict__ Wn,
                      const float* __restrict__ attn) {
    __shared__ float sr[D];
    int r = blockIdx.x, j = threadIdx.x;
    sr[j] = rel[r * D + j];
    __syncthreads();
    float acc = 0.0f;
    #pragma unroll
    for (int k = 0; k < D; k++) acc = fmaf(sr[k], Wn[(D + k) * D + j], acc);
    g_relW[r * D + j] = acc;
    if (j == 0) {
        float s = 0.0f;
        #pragma unroll
        for (int k = 0; k < D; k++) s = fmaf(sr[k], attn[2 * D + k], s);
        g_srel[r] = s;
    }
}

// 3) histogram of dst
__global__ void k_hist(const int* __restrict__ dst) {
    int e = blockIdx.x * blockDim.x + threadIdx.x;
    if (e < N_EDGES) atomicAdd(&g_cnt[dst[e]], 1);
}

// 4a) per-block exclusive scan of g_cnt (512 elements/block) -> g_off, block totals
__global__ void k_scan1() {
    __shared__ int ws[16];
    int i = blockIdx.x * 512 + threadIdx.x;
    int lane = threadIdx.x & 31, wid = threadIdx.x >> 5;
    int v = (i < N_NODES) ? g_cnt[i] : 0;
    int s = warp_incl_scan(v);
    if (lane == 31) ws[wid] = s;
    __syncthreads();
    if (wid == 0) {
        int t = (lane < 16) ? ws[lane] : 0;
        int ts = warp_incl_scan(t);
        if (lane < 16) ws[lane] = ts;
    }
    __syncthreads();
    int excl = s - v + (wid > 0 ? ws[wid - 1] : 0);
    if (i < N_NODES) g_off[i] = excl;
    if (threadIdx.x == 0) g_bsum[blockIdx.x] = ws[15];
}

// 4b) exclusive scan of the SCAN_NB block sums (single block)
__global__ void k_scan2() {
    __shared__ int ws[8];
    int tid = threadIdx.x;
    int lane = tid & 31, wid = tid >> 5;
    int v = (tid < SCAN_NB) ? g_bsum[tid] : 0;
    int s = warp_incl_scan(v);
    if (lane == 31) ws[wid] = s;
    __syncthreads();
    if (wid == 0) {
        int t = (lane < 8) ? ws[lane] : 0;
        int ts = warp_incl_scan(t);
        if (lane < 8) ws[lane] = ts;
    }
    __syncthreads();
    int excl = s - v + (wid > 0 ? ws[wid - 1] : 0);
    if (tid < SCAN_NB) g_bsum[tid] = excl;
}

// 4c) add block offsets; init cursors; cap sentinel
__global__ void k_scan3() {
    int i = blockIdx.x * 512 + threadIdx.x;
    if (i < N_NODES) {
        int o = g_off[i] + g_bsum[blockIdx.x];
        g_off[i] = o;
        g_cur[i] = o;
    }
    if (i == 0) g_off[N_NODES] = N_EDGES;
}

// 5) scatter: compute ex = exp(score), write dst-sorted (pk, ex)
__global__ void k_scatter(const float* __restrict__ etime, const int* __restrict__ src,
                          const int* __restrict__ dst, const int* __restrict__ etype,
                          const float* __restrict__ delta) {
    int e = blockIdx.x * blockDim.x + threadIdx.x;
    if (e >= N_EDGES) return;
    int dd = dst[e], ss = src[e], et = etype[e];
    float v = g_ssrc[ss] + g_sdst[dd] + g_srel[et];
    v = v > 0.0f ? v : SLOPE * v;
    float ex = __expf(-etime[e] * delta[0] * v);
    int pos = atomicAdd(&g_cur[dd], 1);
    g_pk[pos] = (ss << 8) | et;
    g_ex[pos] = ex;
}

// 6) fused aggregate + softmax normalize + loop matvec + final write.
//    One warp per node (grid-stride). Atomic-free.
__global__ void __launch_bounds__(256) k_agg(const float* __restrict__ h,
                                             const float* __restrict__ Wl,
                                             const float* __restrict__ We,
                                             float* __restrict__ out) {
    __shared__ float sWl[D * D];
    __shared__ float sWe[D * D];
    for (int i = threadIdx.x; i < D * D; i += 256) { sWl[i] = Wl[i]; sWe[i] = We[i]; }
    __syncthreads();
    int lane = threadIdx.x & 31;
    int totalWarps = gridDim.x * 8;
    const float2* hW2   = (const float2*)g_hW;
    const float2* relW2 = (const float2*)g_relW;
    const float2* h2p   = (const float2*)h;
    float2* out2        = (float2*)out;

    for (int node = blockIdx.x * 8 + (threadIdx.x >> 5); node < N_NODES;
         node += totalWarps) {
        int beg = g_off[node], end = g_off[node + 1];
        float den = 0.0f, ax = 0.0f, ay = 0.0f;
        for (int i = beg; i < end; i += 32) {
            int idx = i + lane;
            int   pk = (idx < end) ? g_pk[idx] : 0;
            float ex = (idx < end) ? g_ex[idx] : 0.0f;
            int cnt = min(32, end - i);
            for (int t = 0; t < cnt; t++) {
                int   p = __shfl_sync(0xffffffffu, pk, t);
                float x = __shfl_sync(0xffffffffu, ex, t);
                den += x;
                int s = p >> 8, et = p & 255;
                float2 hv = hW2[s * 32 + lane];
                float2 rv = relW2[et * 32 + lane];
                ax = fmaf(x, hv.x + rv.x, ax);
                ay = fmaf(x, hv.y + rv.y, ay);
            }
        }
        bool has = end > beg;
        float2 hrow = h2p[node * 32 + lane];   // features (2*lane, 2*lane+1)
        const float* W = has ? sWl : sWe;
        float lx = 0.0f, ly = 0.0f;
        #pragma unroll
        for (int k = 0; k < 32; k++) {
            float ha = __shfl_sync(0xffffffffu, hrow.x, k);  // h[2k]
            float hb = __shfl_sync(0xffffffffu, hrow.y, k);  // h[2k+1]
            float2 w0 = ((const float2*)W)[(2 * k)     * 32 + lane];
            float2 w1 = ((const float2*)W)[(2 * k + 1) * 32 + lane];
            lx = fmaf(ha, w0.x, fmaf(hb, w1.x, lx));
            ly = fmaf(ha, w0.y, fmaf(hb, w1.y, ly));
        }
        float inv = has ? __fdividef(1.0f, den) : 0.0f;
        float bx = has ? ax * inv : hrow.x;
        float by = has ? ay * inv : hrow.y;
        out2[node * 32 + lane] = make_float2(bx + lx, by + ly);
    }
}

extern "C" void kernel_launch(void* const* d_in, const int* in_sizes, int n_in,
                              void* d_out, int out_size) {
    const float* h     = (const float*)d_in[0];
    const float* rel   = (const float*)d_in[1];
    const float* Wn    = (const float*)d_in[2];
    const float* attn  = (const float*)d_in[3];
    const float* delta = (const float*)d_in[4];
    const float* Wl    = (const float*)d_in[5];
    const float* We    = (const float*)d_in[6];
    const float* etime = (const float*)d_in[7];
    const int*   src   = (const int*)d_in[8];
    const int*   dst   = (const int*)d_in[9];
    const int*   etype = (const int*)d_in[10];
    float* out = (float*)d_out;

    k_zero   <<<391, 256>>>();
    k_hw_s   <<<25000, 256>>>(h, Wn, attn);
    k_rel    <<<N_RELS, 64>>>(rel, Wn, attn);
    k_hist   <<<6250, 256>>>(dst);
    k_scan1  <<<SCAN_NB, 512>>>();
    k_scan2  <<<1, 256>>>();
    k_scan3  <<<SCAN_NB, 512>>>();
    k_scatter<<<6250, 256>>>(etime, src, dst, etype, delta);
    k_agg    <<<1184, 256>>>(h, Wl, We, out);   // 8 warps/block, grid-stride
}